// round 1
// baseline (speedup 1.0000x reference)
#include <cuda_runtime.h>
#include <cuda_bf16.h>
#include <cstdint>

#define N_ROWS 4096
#define D_DIM  512
#define NUM_CL 512
#define MARGIN 0.3f

// ---------------- device scratch (no allocs allowed) ----------------
__device__ float    g_sq[N_ROWS];
__device__ unsigned g_ap[N_ROWS];          // max intra-class dist (bits)
__device__ unsigned g_an[N_ROWS];          // min inter-class dist (bits)
__device__ float    g_cp[N_ROWS];
__device__ float    g_cn[N_ROWS];
__device__ float    g_csum[NUM_CL * D_DIM];
__device__ int      g_ccnt[NUM_CL];
__device__ float    g_tot[D_DIM];
__device__ float    g_cc;

// ---------------- helpers ----------------
__device__ __forceinline__ float blockReduceSum(float v, float* sh) {
    int tid = threadIdx.x;
    #pragma unroll
    for (int o = 16; o; o >>= 1) v += __shfl_down_sync(0xffffffffu, v, o);
    __syncthreads();
    if ((tid & 31) == 0) sh[tid >> 5] = v;
    __syncthreads();
    int nw = (blockDim.x + 31) >> 5;
    if (tid < 32) {
        v = (tid < nw) ? sh[tid] : 0.f;
        #pragma unroll
        for (int o = 16; o; o >>= 1) v += __shfl_down_sync(0xffffffffu, v, o);
    }
    return v;  // valid on tid 0
}

// ---------------- kernels ----------------
__global__ void init_kernel() {
    int i = blockIdx.x * blockDim.x + threadIdx.x;
    if (i < N_ROWS) { g_ap[i] = 0u; g_an[i] = 0x7f800000u; }
    if (i == 0) g_cc = 0.f;
}

// one block per row: squared L2 norm
__global__ void sq_kernel(const float* __restrict__ X) {
    __shared__ float sh[4];
    int r = blockIdx.x;
    const float4 v = *(const float4*)&X[(size_t)r * D_DIM + threadIdx.x * 4];
    float a = v.x * v.x + v.y * v.y + v.z * v.z + v.w * v.w;
    a = blockReduceSum(a, sh);
    if (threadIdx.x == 0) g_sq[r] = a;
}

// one block per class: deterministic class sum + count
__global__ void classsum_kernel(const float* __restrict__ X, const int* __restrict__ T) {
    int c = blockIdx.x;
    int tid = threadIdx.x;  // 256 threads, 2 dims each
    float a0 = 0.f, a1 = 0.f;
    int cnt = 0;
    for (int r = 0; r < N_ROWS; r++) {
        if (T[r] == c) {
            cnt++;
            a0 += X[(size_t)r * D_DIM + tid];
            a1 += X[(size_t)r * D_DIM + tid + 256];
        }
    }
    g_csum[c * D_DIM + tid]       = a0;
    g_csum[c * D_DIM + tid + 256] = a1;
    if (tid == 0) g_ccnt[c] = cnt;
}

// single block: total sums over all classes
__global__ void tot_kernel() {
    int d = threadIdx.x;  // 512 threads
    float s = 0.f;
    for (int c = 0; c < NUM_CL; c++) s += g_csum[c * D_DIM + d];
    g_tot[d] = s;
}

// ------- fused distance GEMM + masked row max/min -------
#define BM 128
#define BN 128
#define BK 16
#define TM 8
#define TN 8

__global__ void __launch_bounds__(256)
dist_kernel(const float* __restrict__ X, const int* __restrict__ T) {
    __shared__ float As[BK][BM];
    __shared__ float Bs[BK][BN];
    __shared__ float sqR[BM], sqC[BN];
    __shared__ int   tR[BM],  tC[BN];
    __shared__ unsigned apS[BM], anS[BM];

    const int tid = threadIdx.x;
    const int rowBase = blockIdx.y * BM;
    const int colBase = blockIdx.x * BN;

    if (tid < 128) {
        sqR[tid] = g_sq[rowBase + tid];
        sqC[tid] = g_sq[colBase + tid];
        tR[tid]  = T[rowBase + tid];
        tC[tid]  = T[colBase + tid];
        apS[tid] = 0u;
        anS[tid] = 0x7f800000u;
    }

    float acc[TM][TN];
    #pragma unroll
    for (int i = 0; i < TM; i++)
        #pragma unroll
        for (int j = 0; j < TN; j++) acc[i][j] = 0.f;

    const int tr = tid >> 4;   // 0..15
    const int tc = tid & 15;   // 0..15

    for (int k0 = 0; k0 < D_DIM; k0 += BK) {
        #pragma unroll
        for (int it = 0; it < 2; it++) {
            int f = tid + it * 256;           // 0..511 float4 slots
            int r = f >> 2, q = f & 3;
            float4 va = *(const float4*)&X[(size_t)(rowBase + r) * D_DIM + k0 + q * 4];
            As[q * 4 + 0][r] = va.x; As[q * 4 + 1][r] = va.y;
            As[q * 4 + 2][r] = va.z; As[q * 4 + 3][r] = va.w;
            float4 vb = *(const float4*)&X[(size_t)(colBase + r) * D_DIM + k0 + q * 4];
            Bs[q * 4 + 0][r] = vb.x; Bs[q * 4 + 1][r] = vb.y;
            Bs[q * 4 + 2][r] = vb.z; Bs[q * 4 + 3][r] = vb.w;
        }
        __syncthreads();
        #pragma unroll
        for (int k = 0; k < BK; k++) {
            float ra[TM], rb[TN];
            *(float4*)&ra[0] = *(const float4*)&As[k][tr * TM];
            *(float4*)&ra[4] = *(const float4*)&As[k][tr * TM + 4];
            *(float4*)&rb[0] = *(const float4*)&Bs[k][tc * TN];
            *(float4*)&rb[4] = *(const float4*)&Bs[k][tc * TN + 4];
            #pragma unroll
            for (int i = 0; i < TM; i++)
                #pragma unroll
                for (int j = 0; j < TN; j++)
                    acc[i][j] = fmaf(ra[i], rb[j], acc[i][j]);
        }
        __syncthreads();
    }

    // epilogue: dist + masked max/min per row
    float apL[TM], anL[TM];
    #pragma unroll
    for (int i = 0; i < TM; i++) { apL[i] = 0.f; anL[i] = __int_as_float(0x7f800000); }

    #pragma unroll
    for (int i = 0; i < TM; i++) {
        const float sqi = sqR[tr * TM + i];
        const int   ti  = tR[tr * TM + i];
        #pragma unroll
        for (int j = 0; j < TN; j++) {
            float d2 = sqi + sqC[tc * TN + j] - 2.f * acc[i][j];
            float d  = sqrtf(fmaxf(d2, 1e-12f));
            if (ti == tC[tc * TN + j]) apL[i] = fmaxf(apL[i], d);
            else                       anL[i] = fminf(anL[i], d);
        }
    }
    #pragma unroll
    for (int i = 0; i < TM; i++) {
        atomicMax(&apS[tr * TM + i], __float_as_uint(apL[i]));
        atomicMin(&anS[tr * TM + i], __float_as_uint(anL[i]));
    }
    __syncthreads();
    if (tid < 128) {
        atomicMax(&g_ap[rowBase + tid], apS[tid]);
        atomicMin(&g_an[rowBase + tid], anS[tid]);
    }
}

// one block per row: centroid distances
__global__ void centroid_kernel(const float* __restrict__ X, const int* __restrict__ T) {
    __shared__ float sh[4];
    int i = blockIdx.x;
    int c = T[i];
    float cnt = (float)g_ccnt[c];
    float a1 = 0.f, a2 = 0.f;
    for (int d = threadIdx.x; d < D_DIM; d += 128) {
        float cs = g_csum[c * D_DIM + d];
        float x  = X[(size_t)i * D_DIM + d];
        float tt = g_tot[d];
        float ic = cs / cnt - x;
        float oc = (tt - cs) / ((float)N_ROWS - cnt) - x;
        a1 += ic * ic;
        a2 += oc * oc;
    }
    a1 = blockReduceSum(a1, sh);
    __syncthreads();
    a2 = blockReduceSum(a2, sh);
    if (threadIdx.x == 0) { g_cp[i] = sqrtf(a1); g_cn[i] = sqrtf(a2); }
}

// one block per class: cc term (count-weighted centroid separation)
__global__ void cc_kernel() {
    __shared__ float sh[4];
    int c = blockIdx.x;
    int cnt = g_ccnt[c];
    if (cnt == 0) return;  // class absent -> contributes nothing
    float fc = (float)cnt;
    float a = 0.f;
    for (int d = threadIdx.x; d < D_DIM; d += 128) {
        float cs = g_csum[c * D_DIM + d];
        float diff = cs / fc - (g_tot[d] - cs) / ((float)N_ROWS - fc);
        a += diff * diff;
    }
    a = blockReduceSum(a, sh);
    if (threadIdx.x == 0) atomicAdd(&g_cc, fc * sqrtf(a));
}

// single block: final scalar reduction
__global__ void final_kernel(float* __restrict__ out) {
    __shared__ float sh[8];
    float s1 = 0.f, s2 = 0.f;
    for (int i = threadIdx.x; i < N_ROWS; i += 256) {
        float ap = __uint_as_float(g_ap[i]);
        float an = __uint_as_float(g_an[i]);
        s1 += fmaxf(ap - an + MARGIN, 0.f);
        s2 += fmaxf(g_cp[i] - g_cn[i] + MARGIN, 0.f);
    }
    s1 = blockReduceSum(s1, sh);
    __syncthreads();
    s2 = blockReduceSum(s2, sh);
    if (threadIdx.x == 0) {
        out[0] = s1 / (float)N_ROWS;
        out[1] = s2 / (float)N_ROWS;
        out[2] = -g_cc / (float)N_ROWS;
    }
}

// ---------------- entry ----------------
extern "C" void kernel_launch(void* const* d_in, const int* in_sizes, int n_in,
                              void* d_out, int out_size) {
    const float* X = (const float*)d_in[0];
    const int*   T = (const int*)d_in[1];
    float* out = (float*)d_out;

    init_kernel<<<(N_ROWS + 255) / 256, 256>>>();
    sq_kernel<<<N_ROWS, 128>>>(X);
    classsum_kernel<<<NUM_CL, 256>>>(X, T);
    tot_kernel<<<1, D_DIM>>>();

    dim3 grid(N_ROWS / BN, N_ROWS / BM);
    dist_kernel<<<grid, 256>>>(X, T);

    centroid_kernel<<<N_ROWS, 128>>>(X, T);
    cc_kernel<<<NUM_CL, 128>>>();
    final_kernel<<<1, 256>>>(out);
}

// round 3
// speedup vs baseline: 2.5790x; 2.5790x over previous
#include <cuda_runtime.h>
#include <cuda_bf16.h>
#include <cstdint>

#define N_ROWS 4096
#define D_DIM  512
#define NUM_CL 512
#define MARGIN 0.3f
#define NCH    8

// ---------------- device scratch ----------------
__device__ float    g_sq[N_ROWS];
__device__ unsigned g_ap[N_ROWS];          // max intra-class dist^2 (bits)
__device__ unsigned g_an[N_ROWS];          // min inter-class dist^2 (bits)
__device__ float    g_cp[N_ROWS];
__device__ float    g_cn[N_ROWS];
__device__ float    g_csum[NUM_CL * D_DIM];
__device__ int      g_ccnt[NUM_CL];
__device__ float    g_tot[D_DIM];
__device__ float    g_cc;
__device__ __align__(16) __nv_bfloat16 g_xb[N_ROWS * D_DIM];
__device__ float    g_cspart[NCH][NUM_CL][D_DIM];
__device__ int      g_ccnt_part[NCH][NUM_CL];

// ---------------- helpers ----------------
__device__ __forceinline__ uint32_t smem_u32(const void* p) {
    uint32_t a;
    asm("{ .reg .u64 t; cvta.to.shared.u64 t, %1; cvt.u32.u64 %0, t; }" : "=r"(a) : "l"(p));
    return a;
}
__device__ __forceinline__ float blockReduceSum(float v, float* sh) {
    int tid = threadIdx.x;
    #pragma unroll
    for (int o = 16; o; o >>= 1) v += __shfl_down_sync(0xffffffffu, v, o);
    __syncthreads();
    if ((tid & 31) == 0) sh[tid >> 5] = v;
    __syncthreads();
    int nw = (blockDim.x + 31) >> 5;
    if (tid < 32) {
        v = (tid < nw) ? sh[tid] : 0.f;
        #pragma unroll
        for (int o = 16; o; o >>= 1) v += __shfl_down_sync(0xffffffffu, v, o);
    }
    return v;
}

// ---------------- prep kernels ----------------
__global__ void init_kernel() {
    int i = blockIdx.x * blockDim.x + threadIdx.x;
    if (i < N_ROWS) { g_ap[i] = 0u; g_an[i] = 0x7f800000u; }
    if (i == 0) g_cc = 0.f;
}

// fused: fp32 -> bf16 conversion + squared norms. one block (128 thr) per row
__global__ void convsq_kernel(const float* __restrict__ X) {
    __shared__ float sh[4];
    int r = blockIdx.x, t = threadIdx.x;
    const float4 v = *(const float4*)&X[(size_t)r * D_DIM + t * 4];
    __nv_bfloat162 lo = __floats2bfloat162_rn(v.x, v.y);
    __nv_bfloat162 hi = __floats2bfloat162_rn(v.z, v.w);
    *(__nv_bfloat162*)&g_xb[(size_t)r * D_DIM + t * 4]     = lo;
    *(__nv_bfloat162*)&g_xb[(size_t)r * D_DIM + t * 4 + 2] = hi;
    float a = v.x * v.x + v.y * v.y + v.z * v.z + v.w * v.w;
    a = blockReduceSum(a, sh);
    if (t == 0) g_sq[r] = a;
}

__global__ void classsum_part(const float* __restrict__ X, const int* __restrict__ T) {
    int c = blockIdx.x, ch = blockIdx.y;
    int tid = threadIdx.x;   // 256
    float a0 = 0.f, a1 = 0.f;
    int cnt = 0;
    int r0 = ch * (N_ROWS / NCH);
    for (int r = r0; r < r0 + N_ROWS / NCH; r++) {
        if (T[r] == c) {
            cnt++;
            a0 += X[(size_t)r * D_DIM + tid];
            a1 += X[(size_t)r * D_DIM + tid + 256];
        }
    }
    g_cspart[ch][c][tid]       = a0;
    g_cspart[ch][c][tid + 256] = a1;
    if (tid == 0) g_ccnt_part[ch][c] = cnt;
}

__global__ void classsum_reduce() {
    int c = blockIdx.x, tid = threadIdx.x;  // 256
    float a0 = 0.f, a1 = 0.f;
    #pragma unroll
    for (int ch = 0; ch < NCH; ch++) {
        a0 += g_cspart[ch][c][tid];
        a1 += g_cspart[ch][c][tid + 256];
    }
    g_csum[c * D_DIM + tid]       = a0;
    g_csum[c * D_DIM + tid + 256] = a1;
    if (tid == 0) {
        int s = 0;
        #pragma unroll
        for (int ch = 0; ch < NCH; ch++) s += g_ccnt_part[ch][c];
        g_ccnt[c] = s;
    }
}

__global__ void tot_kernel() {   // grid 512, block 128
    __shared__ float sh[4];
    int d = blockIdx.x;
    float s = 0.f;
    for (int c = threadIdx.x; c < NUM_CL; c += 128) s += g_csum[c * D_DIM + d];
    s = blockReduceSum(s, sh);
    if (threadIdx.x == 0) g_tot[d] = s;
}

// ---------------- tensor-core (mma.sync) distance kernel ----------------
// 128x128 tile/CTA, 8 warps of 64x32, K chunk = 32 (16 stages), double buffered.
// Triangular grid: only bx >= by computed; epilogue updates rows AND cols.
#define KC 32
#define STAGES (D_DIM / KC)   // 16

__device__ __forceinline__ void ldmx4(uint32_t& r0, uint32_t& r1, uint32_t& r2, uint32_t& r3,
                                      uint32_t addr) {
    asm volatile("ldmatrix.sync.aligned.m8n8.x4.shared.b16 {%0,%1,%2,%3}, [%4];"
                 : "=r"(r0), "=r"(r1), "=r"(r2), "=r"(r3) : "r"(addr));
}
__device__ __forceinline__ void mma_bf16(float* c, uint32_t a0, uint32_t a1, uint32_t a2,
                                         uint32_t a3, uint32_t b0, uint32_t b1) {
    asm volatile("mma.sync.aligned.m16n8k16.row.col.f32.bf16.bf16.f32 "
                 "{%0,%1,%2,%3}, {%4,%5,%6,%7}, {%8,%9}, {%0,%1,%2,%3};"
                 : "+f"(c[0]), "+f"(c[1]), "+f"(c[2]), "+f"(c[3])
                 : "r"(a0), "r"(a1), "r"(a2), "r"(a3), "r"(b0), "r"(b1));
}
#define CP16(dst, src) \
    asm volatile("cp.async.cg.shared.global [%0], [%1], 16;" :: "r"(dst), "l"(src))
#define CP_COMMIT() asm volatile("cp.async.commit_group;" ::: "memory")

__global__ void __launch_bounds__(256, 2)
dist_mma_kernel(const int* __restrict__ T) {
    if (blockIdx.x < blockIdx.y) return;   // upper triangle only

    __shared__ __align__(1024) __nv_bfloat16 smA[2][128 * KC];
    __shared__ __align__(1024) __nv_bfloat16 smB[2][128 * KC];
    __shared__ float sqRs[128], sqCs[128];
    __shared__ int   tRs[128], tCs[128];
    __shared__ unsigned apS[128], anS[128], apSc[128], anSc[128];

    const int tid = threadIdx.x, wid = tid >> 5, lane = tid & 31;
    const int rowBase = blockIdx.y * 128;
    const int colBase = blockIdx.x * 128;
    const int warpM = (wid >> 2) * 64;
    const int warpN = (wid & 3) * 32;

    if (tid < 128) {
        sqRs[tid] = g_sq[rowBase + tid];
        sqCs[tid] = g_sq[colBase + tid];
        tRs[tid]  = T[rowBase + tid];
        tCs[tid]  = T[colBase + tid];
        apS[tid] = 0u;  anS[tid] = 0x7f800000u;
        apSc[tid] = 0u; anSc[tid] = 0x7f800000u;
    }

    const uint32_t sbA = smem_u32(&smA[0][0]);
    const uint32_t sbB = smem_u32(&smB[0][0]);
    const char* Xb = (const char*)g_xb;

    // loader lanes: r = f>>2 (row 0..127), u = f&3 (16B unit)
    const int lr = tid >> 1;            // not used directly; loads use f decomposition
    (void)lr;

    // per-lane ldmatrix address precompute
    const int aRow  = warpM + (lane & 15);
    const int aKH   = (lane >> 4) * 16;                  // k-half byte offset
    const uint32_t aXor = (((unsigned)aRow >> 1) & 3u) << 4;
    const int nRow  = warpN + (lane & 7) + ((lane >> 4) << 3);  // matrices 0,1: n0-7; 2,3: n8-15
    const int bKH   = ((lane >> 3) & 1) * 16;
    const uint32_t bXor = (((unsigned)nRow >> 1) & 3u) << 4;

    float acc[4][4][4];
    #pragma unroll
    for (int i = 0; i < 4; i++)
        #pragma unroll
        for (int j = 0; j < 4; j++)
            #pragma unroll
            for (int c = 0; c < 4; c++) acc[i][j][c] = 0.f;

    // ---- prologue: stage 0 into buf 0 ----
    {
        const int koff = 0;
        #pragma unroll
        for (int it = 0; it < 2; it++) {
            int f = tid + it * 256;
            int r = f >> 2, u = f & 3;
            uint32_t so = (uint32_t)(r * 64 + ((u * 16) ^ (((r >> 1) & 3) << 4)));
            CP16(sbA + so, Xb + (((size_t)(rowBase + r)) * D_DIM + koff + u * 8) * 2);
            CP16(sbB + so, Xb + (((size_t)(colBase + r)) * D_DIM + koff + u * 8) * 2);
        }
        CP_COMMIT();
    }

    for (int s = 0; s < STAGES; s++) {
        const int buf = s & 1;
        if (s < STAGES - 1) {
            const int koff = (s + 1) * KC;
            const uint32_t bo = (uint32_t)((buf ^ 1) * 128 * KC * 2);
            #pragma unroll
            for (int it = 0; it < 2; it++) {
                int f = tid + it * 256;
                int r = f >> 2, u = f & 3;
                uint32_t so = bo + (uint32_t)(r * 64 + ((u * 16) ^ (((r >> 1) & 3) << 4)));
                CP16(sbA + so, Xb + (((size_t)(rowBase + r)) * D_DIM + koff + u * 8) * 2);
                CP16(sbB + so, Xb + (((size_t)(colBase + r)) * D_DIM + koff + u * 8) * 2);
            }
            CP_COMMIT();
            asm volatile("cp.async.wait_group 1;" ::: "memory");
        } else {
            asm volatile("cp.async.wait_group 0;" ::: "memory");
        }
        __syncthreads();

        const uint32_t bufOff = (uint32_t)(buf * 128 * KC * 2);
        #pragma unroll
        for (int ks = 0; ks < 2; ks++) {
            uint32_t b[4][2];
            #pragma unroll
            for (int nb = 0; nb < 2; nb++) {
                uint32_t addr = sbB + bufOff + (uint32_t)((nRow + nb * 16) * 64)
                              + (uint32_t)((ks * 32 + bKH) ^ bXor);
                uint32_t q0, q1, q2, q3;
                ldmx4(q0, q1, q2, q3, addr);
                b[nb * 2][0] = q0; b[nb * 2][1] = q1;
                b[nb * 2 + 1][0] = q2; b[nb * 2 + 1][1] = q3;
            }
            #pragma unroll
            for (int mi = 0; mi < 4; mi++) {
                uint32_t addr = sbA + bufOff + (uint32_t)((aRow + mi * 16) * 64)
                              + (uint32_t)((ks * 32 + aKH) ^ aXor);
                uint32_t a0, a1, a2, a3;
                ldmx4(a0, a1, a2, a3, addr);
                #pragma unroll
                for (int nj = 0; nj < 4; nj++)
                    mma_bf16(acc[mi][nj], a0, a1, a2, a3, b[nj][0], b[nj][1]);
            }
        }
        __syncthreads();
    }

    // ---- epilogue ----
    const int g = lane >> 2, q = lane & 3;
    const float INF = __int_as_float(0x7f800000);

    // pass 1: row-wise max/min; also overwrite acc with clamped d^2
    #pragma unroll
    for (int mi = 0; mi < 4; mi++) {
        #pragma unroll
        for (int half = 0; half < 2; half++) {
            const int row = warpM + mi * 16 + g + half * 8;
            const float sqi = sqRs[row];
            const int   ti  = tRs[row];
            float ap = 0.f, an = INF;
            #pragma unroll
            for (int nj = 0; nj < 4; nj++) {
                #pragma unroll
                for (int c = 0; c < 2; c++) {
                    const int col = warpN + nj * 8 + q * 2 + c;
                    float d2 = fmaxf(sqi + sqCs[col] - 2.f * acc[mi][nj][half * 2 + c], 1e-12f);
                    acc[mi][nj][half * 2 + c] = d2;
                    if (ti == tCs[col]) ap = fmaxf(ap, d2);
                    else                an = fminf(an, d2);
                }
            }
            ap = fmaxf(ap, __shfl_xor_sync(0xffffffffu, ap, 1));
            ap = fmaxf(ap, __shfl_xor_sync(0xffffffffu, ap, 2));
            an = fminf(an, __shfl_xor_sync(0xffffffffu, an, 1));
            an = fminf(an, __shfl_xor_sync(0xffffffffu, an, 2));
            if (q == 0) {
                atomicMax(&apS[row], __float_as_uint(ap));
                atomicMin(&anS[row], __float_as_uint(an));
            }
        }
    }
    // pass 2: column-wise max/min (symmetry)
    #pragma unroll
    for (int nj = 0; nj < 4; nj++) {
        #pragma unroll
        for (int c = 0; c < 2; c++) {
            const int col = warpN + nj * 8 + q * 2 + c;
            const int tc = tCs[col];
            float ap = 0.f, an = INF;
            #pragma unroll
            for (int mi = 0; mi < 4; mi++) {
                #pragma unroll
                for (int half = 0; half < 2; half++) {
                    const int row = warpM + mi * 16 + g + half * 8;
                    float d2 = acc[mi][nj][half * 2 + c];
                    if (tRs[row] == tc) ap = fmaxf(ap, d2);
                    else                an = fminf(an, d2);
                }
            }
            ap = fmaxf(ap, __shfl_xor_sync(0xffffffffu, ap, 4));
            ap = fmaxf(ap, __shfl_xor_sync(0xffffffffu, ap, 8));
            ap = fmaxf(ap, __shfl_xor_sync(0xffffffffu, ap, 16));
            an = fminf(an, __shfl_xor_sync(0xffffffffu, an, 4));
            an = fminf(an, __shfl_xor_sync(0xffffffffu, an, 8));
            an = fminf(an, __shfl_xor_sync(0xffffffffu, an, 16));
            if (g == 0) {
                atomicMax(&apSc[col], __float_as_uint(ap));
                atomicMin(&anSc[col], __float_as_uint(an));
            }
        }
    }
    __syncthreads();
    if (tid < 128) {
        atomicMax(&g_ap[rowBase + tid], apS[tid]);
        atomicMin(&g_an[rowBase + tid], anS[tid]);
        atomicMax(&g_ap[colBase + tid], apSc[tid]);
        atomicMin(&g_an[colBase + tid], anSc[tid]);
    }
}

// ---------------- centroid / cc / final ----------------
__global__ void centroid_kernel(const float* __restrict__ X, const int* __restrict__ T) {
    __shared__ float sh[4];
    int i = blockIdx.x;
    int c = T[i];
    float cnt = (float)g_ccnt[c];
    float a1 = 0.f, a2 = 0.f;
    for (int d = threadIdx.x; d < D_DIM; d += 128) {
        float cs = g_csum[c * D_DIM + d];
        float x  = X[(size_t)i * D_DIM + d];
        float tt = g_tot[d];
        float ic = cs / cnt - x;
        float oc = (tt - cs) / ((float)N_ROWS - cnt) - x;
        a1 += ic * ic;
        a2 += oc * oc;
    }
    a1 = blockReduceSum(a1, sh);
    __syncthreads();
    a2 = blockReduceSum(a2, sh);
    if (threadIdx.x == 0) { g_cp[i] = sqrtf(a1); g_cn[i] = sqrtf(a2); }
}

__global__ void cc_kernel() {
    __shared__ float sh[4];
    int c = blockIdx.x;
    int cnt = g_ccnt[c];
    if (cnt == 0) return;
    float fc = (float)cnt;
    float a = 0.f;
    for (int d = threadIdx.x; d < D_DIM; d += 128) {
        float cs = g_csum[c * D_DIM + d];
        float diff = cs / fc - (g_tot[d] - cs) / ((float)N_ROWS - fc);
        a += diff * diff;
    }
    a = blockReduceSum(a, sh);
    if (threadIdx.x == 0) atomicAdd(&g_cc, fc * sqrtf(a));
}

__global__ void final_kernel(float* __restrict__ out) {
    __shared__ float sh[8];
    float s1 = 0.f, s2 = 0.f;
    for (int i = threadIdx.x; i < N_ROWS; i += 256) {
        float ap = sqrtf(__uint_as_float(g_ap[i]));
        float an = sqrtf(__uint_as_float(g_an[i]));
        s1 += fmaxf(ap - an + MARGIN, 0.f);
        s2 += fmaxf(g_cp[i] - g_cn[i] + MARGIN, 0.f);
    }
    s1 = blockReduceSum(s1, sh);
    __syncthreads();
    s2 = blockReduceSum(s2, sh);
    if (threadIdx.x == 0) {
        out[0] = s1 / (float)N_ROWS;
        out[1] = s2 / (float)N_ROWS;
        out[2] = -g_cc / (float)N_ROWS;
    }
}

// ---------------- entry ----------------
extern "C" void kernel_launch(void* const* d_in, const int* in_sizes, int n_in,
                              void* d_out, int out_size) {
    const float* X = (const float*)d_in[0];
    const int*   T = (const int*)d_in[1];
    float* out = (float*)d_out;

    init_kernel<<<(N_ROWS + 255) / 256, 256>>>();
    convsq_kernel<<<N_ROWS, 128>>>(X);

    dim3 csg(NUM_CL, NCH);
    classsum_part<<<csg, 256>>>(X, T);
    classsum_reduce<<<NUM_CL, 256>>>();
    tot_kernel<<<D_DIM, 128>>>();

    dim3 grid(N_ROWS / 128, N_ROWS / 128);
    dist_mma_kernel<<<grid, 256>>>(T);

    centroid_kernel<<<N_ROWS, 128>>>(X, T);
    cc_kernel<<<NUM_CL, 128>>>();
    final_kernel<<<1, 256>>>(out);
}